// round 14
// baseline (speedup 1.0000x reference)
#include <cuda_runtime.h>
#include <cuda_fp16.h>
#include <math.h>
#include <float.h>
#include <stdint.h>

// ---------------------------------------------------------------------------
// NCM few-shot classifier — approximate-then-verify tensor-core pipeline.
//   1) mean over support rows (2-stage deterministic)
//   2) pack: center+normalize; write fp16(hi) rows (K=512) + fp32 normalized
//   3) GEMM: single fp16 pass via mma.sync m16n8k16, 3-stage cp.async ring
//      (one __syncthreads per chunk); per-split TOP-2 (v1,i1,v2) per query
//   4) pick: global approx max; sound threshold TH=2.5e-3 (> 2x worst-case
//      fp16 error ~1.1e-3 on unit vectors). v1<th splits are provably out;
//      v1>=th,v2<th -> one exact fp32 rescore; v2>=th (rare) -> rescore split.
//      Writes class = best/SHOTS as float32; also fills out[nq..out_size).
// ---------------------------------------------------------------------------

#define DIMK    512
#define KP      512
#define SHOTS   5
#define QT      128
#define ST      128
#define CH      64
#define NCHUNK  (KP / CH)     // 8
#define ROWB    144
#define MAXV    5120
#define MAXSPLIT 40
#define MEANBLK 64
#define TH      2.5e-3f

// dynamic smem: 3 stages x (A 18432 + B 18432); epilogue reuses stage 0
#define SM_BUF(b)  ((b) * 36864)
#define SM_BOFF    18432
#define SM_TOTAL   110592

__device__ __align__(16) float  g_part[MEANBLK][DIMK];
__device__ __align__(16) float  g_mean[DIMK];
__device__ __align__(16) __half g_qh[(size_t)MAXV * KP];
__device__ __align__(16) __half g_sh[(size_t)MAXV * KP];
__device__ __align__(16) float  g_qnf[(size_t)MAXV * DIMK];
__device__ __align__(16) float  g_snf[(size_t)MAXV * DIMK];
// per-query split records, [q][split] for coalesced pick-kernel reads
__device__ __align__(16) float  g_b1v[(size_t)MAXV * MAXSPLIT];
__device__ __align__(16) int    g_b1i[(size_t)MAXV * MAXSPLIT];
__device__ __align__(16) float  g_b2v[(size_t)MAXV * MAXSPLIT];

// ---- PTX helpers -------------------------------------------------------------
__device__ __forceinline__ uint32_t smem_u32(const void* p) {
    uint32_t a;
    asm("{ .reg .u64 t; cvta.to.shared.u64 t, %1; cvt.u32.u64 %0, t; }"
        : "=r"(a) : "l"(p));
    return a;
}
__device__ __forceinline__ void cp16(uint32_t dst, const void* src) {
    uint64_t g;
    asm("cvta.to.global.u64 %0, %1;" : "=l"(g) : "l"(src));
    asm volatile("cp.async.cg.shared.global [%0], [%1], 16;"
                 :: "r"(dst), "l"(g) : "memory");
}
__device__ __forceinline__ void cp_commit() {
    asm volatile("cp.async.commit_group;" ::: "memory");
}
template <int N>
__device__ __forceinline__ void cp_wait() {
    asm volatile("cp.async.wait_group %0;" :: "n"(N) : "memory");
}
__device__ __forceinline__ void ldsm_x4(uint32_t& r0, uint32_t& r1,
                                        uint32_t& r2, uint32_t& r3, uint32_t a) {
    asm volatile("ldmatrix.sync.aligned.m8n8.x4.shared.b16 {%0,%1,%2,%3}, [%4];"
                 : "=r"(r0), "=r"(r1), "=r"(r2), "=r"(r3) : "r"(a));
}
__device__ __forceinline__ void mma16816(float* c, const uint32_t* a,
                                         uint32_t b0, uint32_t b1) {
    asm volatile(
        "mma.sync.aligned.m16n8k16.row.col.f32.f16.f16.f32 "
        "{%0,%1,%2,%3}, {%4,%5,%6,%7}, {%8,%9}, {%0,%1,%2,%3};"
        : "+f"(c[0]), "+f"(c[1]), "+f"(c[2]), "+f"(c[3])
        : "r"(a[0]), "r"(a[1]), "r"(a[2]), "r"(a[3]), "r"(b0), "r"(b1));
}

// --- stage 1/2: deterministic support mean -------------------------------------
__global__ void k_mean_part(const float* __restrict__ s, int nrows) {
    int b  = blockIdx.x;
    int d0 = threadIdx.x, d1 = threadIdx.x + 256;
    float a0 = 0.0f, a1 = 0.0f;
    for (int r = b; r < nrows; r += MEANBLK) {
        const float* row = s + (size_t)r * DIMK;
        a0 += row[d0]; a1 += row[d1];
    }
    g_part[b][d0] = a0; g_part[b][d1] = a1;
}
__global__ void k_mean_final(float inv_cnt) {
    int d0 = threadIdx.x, d1 = threadIdx.x + 256;
    float a0 = 0.0f, a1 = 0.0f;
    for (int b = 0; b < MEANBLK; ++b) { a0 += g_part[b][d0]; a1 += g_part[b][d1]; }
    g_mean[d0] = a0 * inv_cnt; g_mean[d1] = a1 * inv_cnt;
}

// --- stage 3: center + normalize; emit fp16(hi) + fp32 rows (warp per row) -----
__global__ void k_pack(const float* __restrict__ sup, const float* __restrict__ qry,
                       int nsup, int nq) {
    int gw   = blockIdx.x * 8 + (threadIdx.x >> 5);
    int lane = threadIdx.x & 31;
    if (gw >= 2 * MAXV) return;
    bool isQ = (gw >= MAXV);
    int  row = isQ ? gw - MAXV : gw;
    __half* dh = (isQ ? g_qh : g_sh) + (size_t)row * KP;
    float*  df = (isQ ? g_qnf : g_snf) + (size_t)row * DIMK;
    bool valid = isQ ? (row < nq) : (row < nsup);
    if (!valid) {                          // zero fp16 pad rows (MMA operands)
        uint4 z = make_uint4(0, 0, 0, 0);
        for (int i = lane; i < (KP * 2) / 16; i += 32) ((uint4*)dh)[i] = z;
        return;
    }
    const float* src = (isQ ? qry : sup) + (size_t)row * DIMK;
    float v[16], nrm = 0.0f;
    #pragma unroll
    for (int i = 0; i < 16; ++i) {
        int k = i * 32 + lane;
        v[i] = src[k] - g_mean[k];
        nrm += v[i] * v[i];
    }
    #pragma unroll
    for (int o = 16; o; o >>= 1) nrm += __shfl_xor_sync(0xffffffffu, nrm, o);
    float rn = 1.0f / sqrtf(nrm);
    #pragma unroll
    for (int i = 0; i < 16; ++i) {
        int k = i * 32 + lane;
        float n = v[i] * rn;
        dh[k] = __float2half(n);
        df[k] = n;
    }
}

// --- stage 4: mma.sync GEMM, 3-stage ring, per-split TOP-2 epilogue -------------
__device__ __forceinline__ void stage_chunk(uint32_t sb, int buf, int kc,
                                            int q0, int sbeg, int tid) {
    const int ko2 = kc * CH * 2;
    uint32_t ab = sb + SM_BUF(buf);
    uint32_t bb = ab + SM_BOFF;
    #pragma unroll
    for (int l = 0; l < 4; ++l) {
        int idx = tid + l * 256;
        int row = idx >> 3, p = idx & 7;
        cp16(ab + row * ROWB + p * 16,
             (const char*)(g_qh + (size_t)(q0 + row) * KP) + ko2 + p * 16);
        cp16(bb + row * ROWB + p * 16,
             (const char*)(g_sh + (size_t)(sbeg + row) * KP) + ko2 + p * 16);
    }
}

__global__ void __launch_bounds__(256, 2)
k_mma_best(int nq, int ns) {
    extern __shared__ __align__(16) char smem[];
    const uint32_t sb = smem_u32(smem);
    const int tid   = threadIdx.x;
    const int lane  = tid & 31;
    const int warp  = tid >> 5;
    const int warpm = warp >> 1;
    const int warpn = warp & 1;
    const int q0    = blockIdx.x * QT;
    const int sbeg  = blockIdx.y * ST;

    float acc[2][8][4];
    #pragma unroll
    for (int mt = 0; mt < 2; ++mt)
        #pragma unroll
        for (int nt = 0; nt < 8; ++nt)
            #pragma unroll
            for (int e = 0; e < 4; ++e) acc[mt][nt][e] = 0.0f;

    // prologue: stage chunks 0 and 1
    stage_chunk(sb, 0, 0, q0, sbeg, tid);
    cp_commit();
    stage_chunk(sb, 1, 1, q0, sbeg, tid);
    cp_commit();

    const int r = lane & 7, g = lane >> 3;
    const int m0 = warpm * 32, n0 = warpn * 64;

    for (int kc = 0; kc < NCHUNK; ++kc) {
        if (kc + 1 < NCHUNK) cp_wait<1>(); else cp_wait<0>();
        __syncthreads();                    // one sync per chunk

        // stage kc+2 into buffer (kc+2)%3 == (kc-1)%3 — safe: all warps have
        // finished computing chunk kc-1 (they passed this barrier).
        if (kc + 2 < NCHUNK) {
            stage_chunk(sb, (kc + 2) % 3, kc + 2, q0, sbeg, tid);
            cp_commit();
        }

        uint32_t ab = sb + SM_BUF(kc % 3);
        uint32_t bb = ab + SM_BOFF;
        #pragma unroll
        for (int ks = 0; ks < 4; ++ks) {
            const int k0 = ks * 16;
            uint32_t a[2][4];
            #pragma unroll
            for (int mt = 0; mt < 2; ++mt) {
                uint32_t addr = ab + (m0 + mt * 16 + ((g & 1) << 3) + r) * ROWB
                                   + (k0 + ((g >> 1) << 3)) * 2;
                ldsm_x4(a[mt][0], a[mt][1], a[mt][2], a[mt][3], addr);
            }
            #pragma unroll
            for (int np = 0; np < 4; ++np) {
                uint32_t b0, b1, b2, b3;
                uint32_t addr = bb + (n0 + np * 16 + ((g >> 1) << 3) + r) * ROWB
                                   + (k0 + ((g & 1) << 3)) * 2;
                ldsm_x4(b0, b1, b2, b3, addr);
                #pragma unroll
                for (int mt = 0; mt < 2; ++mt) {
                    mma16816(acc[mt][np * 2 + 0], a[mt], b0, b1);
                    mma16816(acc[mt][np * 2 + 1], a[mt], b2, b3);
                }
            }
        }
    }
    __syncthreads();   // before reusing stage-0 smem for the epilogue arrays

    // ---- epilogue: per-lane TOP-2 per owned row --------------------------------
    const int group = lane >> 2, tg = lane & 3;
    float v1[4], v2[4];
    int   i1[4];
    #pragma unroll
    for (int i = 0; i < 4; ++i) { v1[i] = -FLT_MAX; v2[i] = -FLT_MAX; i1[i] = MAXV; }

    #pragma unroll
    for (int mt = 0; mt < 2; ++mt)
        #pragma unroll
        for (int nt = 0; nt < 8; ++nt) {
            int c0 = sbeg + n0 + nt * 8 + tg * 2;
            #pragma unroll
            for (int h = 0; h < 2; ++h) {
                int i = mt * 2 + h;
                float a0 = acc[mt][nt][h * 2 + 0];
                float a1 = acc[mt][nt][h * 2 + 1];
                if (c0 < ns) {
                    if (a0 > v1[i]) { v2[i] = v1[i]; v1[i] = a0; i1[i] = c0; }
                    else if (a0 > v2[i]) v2[i] = a0;
                }
                if (c0 + 1 < ns) {
                    if (a1 > v1[i]) { v2[i] = v1[i]; v1[i] = a1; i1[i] = c0 + 1; }
                    else if (a1 > v2[i]) v2[i] = a1;
                }
            }
        }
    #pragma unroll
    for (int o = 1; o < 4; o <<= 1) {
        #pragma unroll
        for (int i = 0; i < 4; ++i) {
            float ov1 = __shfl_xor_sync(0xffffffffu, v1[i], o);
            int   oi1 = __shfl_xor_sync(0xffffffffu, i1[i], o);
            float ov2 = __shfl_xor_sync(0xffffffffu, v2[i], o);
            if (ov1 > v1[i] || (ov1 == v1[i] && oi1 < i1[i])) {
                v2[i] = fmaxf(v1[i], ov2); v1[i] = ov1; i1[i] = oi1;
            } else {
                v2[i] = fmaxf(v2[i], ov1);
            }
        }
    }
    float* s_v1 = (float*)(smem);            // [128][2] — reuses stage-0 smem
    int*   s_i1 = (int*)(smem + 1024);
    float* s_v2 = (float*)(smem + 2048);
    if (tg == 0) {
        #pragma unroll
        for (int mt = 0; mt < 2; ++mt)
            #pragma unroll
            for (int h = 0; h < 2; ++h) {
                int row = m0 + mt * 16 + h * 8 + group;
                s_v1[row * 2 + warpn] = v1[mt * 2 + h];
                s_i1[row * 2 + warpn] = i1[mt * 2 + h];
                s_v2[row * 2 + warpn] = v2[mt * 2 + h];
            }
    }
    __syncthreads();
    if (tid < QT) {
        float a1v = s_v1[tid * 2 + 0], a2v = s_v2[tid * 2 + 0];
        int   a1i = s_i1[tid * 2 + 0];
        float b1v = s_v1[tid * 2 + 1], b2v = s_v2[tid * 2 + 1];
        int   b1i = s_i1[tid * 2 + 1];
        float o1, o2; int oi;
        if (b1v > a1v || (b1v == a1v && b1i < a1i)) {
            o1 = b1v; oi = b1i; o2 = fmaxf(a1v, b2v);
        } else {
            o1 = a1v; oi = a1i; o2 = fmaxf(a2v, b1v);
        }
        int q = q0 + tid;
        size_t rec = (size_t)q * MAXSPLIT + blockIdx.y;
        g_b1v[rec] = o1;
        g_b1i[rec] = oi;
        g_b2v[rec] = o2;
    }
}

// --- stage 5: pick — threshold, exact fp32 rescore, classify (+tail fill) ------
__global__ void __launch_bounds__(128)
k_pick(float* __restrict__ out, int nq, int ns, int nsp) {
    int q = blockIdx.x;
    const int tid  = threadIdx.x;
    if (q >= nq) { if (tid == 0) out[q] = 0.0f; return; }
    const int lane = tid & 31;
    const int warp = tid >> 5;

    __shared__ float sv1[MAXSPLIT], sv2[MAXSPLIT];
    __shared__ int   si1[MAXSPLIT];
    __shared__ int   singles[MAXSPLIT], exh[MAXSPLIT];
    __shared__ int   nsing, nexh;
    __shared__ float wbv[4];
    __shared__ int   wbi[4];

    if (tid < nsp) {                        // coalesced: [q][sp] layout
        size_t rec = (size_t)q * MAXSPLIT + tid;
        sv1[tid] = g_b1v[rec];
        sv2[tid] = g_b2v[rec];
        si1[tid] = g_b1i[rec];
    }
    __syncthreads();
    if (tid == 0) {
        float mx = -FLT_MAX;
        for (int sp = 0; sp < nsp; ++sp) mx = fmaxf(mx, sv1[sp]);
        float th = mx - TH;
        int a = 0, b = 0;
        for (int sp = 0; sp < nsp; ++sp) {
            if (sv1[sp] >= th) {
                if (sv2[sp] >= th) exh[b++] = sp;
                else singles[a++] = si1[sp];
            }
        }
        nsing = a; nexh = b;
    }
    __syncthreads();

    const float* qv = g_qnf + (size_t)q * DIMK;
    float bv = -FLT_MAX;
    int   bi = MAXV;

    for (int ci = warp; ci < nsing; ci += 4) {
        int s = singles[ci];
        const float* svv = g_snf + (size_t)s * DIMK;
        float d = 0.0f;
        #pragma unroll
        for (int i = 0; i < 16; ++i) d += qv[i * 32 + lane] * svv[i * 32 + lane];
        #pragma unroll
        for (int o = 16; o; o >>= 1) d += __shfl_xor_sync(0xffffffffu, d, o);
        if (d > bv || (d == bv && s < bi)) { bv = d; bi = s; }
    }
    for (int e = 0; e < nexh; ++e) {
        int sp = exh[e];
        int sb = sp * ST;
        int se = min(sb + ST, ns);
        for (int s = sb + warp; s < se; s += 4) {
            const float* svv = g_snf + (size_t)s * DIMK;
            float d = 0.0f;
            #pragma unroll
            for (int i = 0; i < 16; ++i) d += qv[i * 32 + lane] * svv[i * 32 + lane];
            #pragma unroll
            for (int o = 16; o; o >>= 1) d += __shfl_xor_sync(0xffffffffu, d, o);
            if (d > bv || (d == bv && s < bi)) { bv = d; bi = s; }
        }
    }
    if (lane == 0) { wbv[warp] = bv; wbi[warp] = bi; }
    __syncthreads();
    if (tid == 0) {
        float fv = wbv[0]; int fi = wbi[0];
        #pragma unroll
        for (int w = 1; w < 4; ++w) {
            if (wbv[w] > fv || (wbv[w] == fv && wbi[w] < fi)) { fv = wbv[w]; fi = wbi[w]; }
        }
        out[q] = (float)(fi / SHOTS);
    }
}

// ---------------------------------------------------------------------------
extern "C" void kernel_launch(void* const* d_in, const int* in_sizes, int n_in,
                              void* d_out, int out_size) {
    const float* sup = (const float*)d_in[0];   // support_features [1000,5,512]
    const float* qry = (const float*)d_in[1];   // query_features   [5000,512]
    // d_in[2] = use_cosine: ignored (decision is mathematically identical)

    int nsup = in_sizes[0] / DIMK;
    int nq   = in_sizes[1] / DIMK;
    if (nsup > MAXV) nsup = MAXV;
    if (nq   > MAXV) nq   = MAXV;
    if (nsup < 1) nsup = 1;
    if (nq   < 1) nq   = 1;
    if (nq > out_size) nq = out_size;

    k_mean_part<<<MEANBLK, 256>>>(sup, nsup);
    k_mean_final<<<1, 256>>>(1.0f / (float)nsup);

    k_pack<<<(2 * MAXV) / 8, 256>>>(sup, qry, nsup, nq);

    int grid_q = (nq + QT - 1) / QT;             // 40
    int nsp    = (nsup + ST - 1) / ST;           // 40
    if (nsp < 1) nsp = 1;
    if (nsp > MAXSPLIT) nsp = MAXSPLIT;

    cudaFuncSetAttribute(k_mma_best,
                         cudaFuncAttributeMaxDynamicSharedMemorySize, SM_TOTAL);
    dim3 grid(grid_q, nsp);
    k_mma_best<<<grid, 256, SM_TOTAL>>>(nq, nsup);

    int pick_grid = (out_size > nq) ? out_size : nq;
    k_pick<<<pick_grid, 128>>>((float*)d_out, nq, nsup, nsp);
}